// round 2
// baseline (speedup 1.0000x reference)
#include <cuda_runtime.h>
#include <math.h>

#define Bb    4
#define Tt    10
#define Nn    2048
#define Ff    64
#define Hh    128
#define NHEAD 4
#define Dd    32
#define Ee    65536
#define NTOT  8192            // B*N
#define MTOT  81920           // T*NTOT
#define G4H   512             // 4*H
#define EFULL (Ee + NTOT)     // edges + self loops

// ---------------- device scratch (no allocations allowed) ----------------
__device__ float g_xflat[MTOT * Ff];
__device__ float g_Wt[Hh * Ff];
__device__ float g_h[MTOT * Hh];
__device__ float g_asrc[MTOT * NHEAD];
__device__ float g_adst[MTOT * NHEAD];
__device__ float g_spatial[MTOT * Hh];
__device__ float g_gih0[(size_t)MTOT * G4H];   // precomputed layer0 input gates, all t
__device__ float g_gates[NTOT * G4H];
__device__ float g_h0[NTOT * Hh];
__device__ float g_c0[NTOT * Hh];
__device__ float g_h1[NTOT * Hh];
__device__ float g_c1[NTOT * Hh];
__device__ float g_bsum0[G4H];
__device__ float g_bsum1[G4H];
__device__ int   g_count[NTOT];
__device__ int   g_off[NTOT + 1];
__device__ int   g_cur[NTOT];
__device__ int   g_csr[EFULL];

// ---------------- small prep kernels ----------------
__global__ void transpose_x(const float* __restrict__ x) {
    int idx = blockIdx.x * blockDim.x + threadIdx.x;
    if (idx >= MTOT * Ff) return;
    int f  = idx & 63;
    int r  = idx >> 6;        // m = (t*B + b)*N + n
    int n  = r & (Nn - 1);
    int bt = r >> 11;         // t*B + b
    int b  = bt & 3;
    int t  = bt >> 2;
    g_xflat[idx] = x[(((size_t)(b * Tt + t) * Nn + n) << 6) + f];
}

__global__ void wt_kernel(const float* __restrict__ W) {
    int i = blockIdx.x * blockDim.x + threadIdx.x;
    if (i >= Hh * Ff) return;
    int n = i >> 6, k = i & 63;
    g_Wt[i] = W[k * Hh + n];   // Wt[n][k] = W[k][n]
}

__global__ void init_kernel(const float* __restrict__ b_ih0, const float* __restrict__ b_hh0,
                            const float* __restrict__ b_ih1, const float* __restrict__ b_hh1) {
    int i = blockIdx.x * blockDim.x + threadIdx.x;
    if (i < NTOT) g_count[i] = 1;  // self loop pre-counted
    if (i < G4H) {
        g_bsum0[i] = b_ih0[i] + b_hh0[i];
        g_bsum1[i] = b_ih1[i] + b_hh1[i];
    }
}

__global__ void zero_state() {
    int i = blockIdx.x * blockDim.x + threadIdx.x;
    if (i >= NTOT * Hh) return;
    g_h0[i] = 0.f; g_c0[i] = 0.f; g_h1[i] = 0.f; g_c1[i] = 0.f;
}

__global__ void count_kernel(const int* __restrict__ ei) {
    int e = blockIdx.x * blockDim.x + threadIdx.x;
    if (e < Ee) atomicAdd(&g_count[ei[Ee + e]], 1);
}

__global__ void scan_kernel() {
    __shared__ int part[256];
    int tid  = threadIdx.x;
    int base = tid * 32;
    int local[32];
    int s = 0;
#pragma unroll
    for (int i = 0; i < 32; i++) { local[i] = g_count[base + i]; s += local[i]; }
    part[tid] = s;
    __syncthreads();
    for (int off = 1; off < 256; off <<= 1) {
        int v = (tid >= off) ? part[tid - off] : 0;
        __syncthreads();
        part[tid] += v;
        __syncthreads();
    }
    int run = part[tid] - s;   // exclusive prefix of this chunk
#pragma unroll
    for (int i = 0; i < 32; i++) {
        g_off[base + i] = run;
        g_cur[base + i] = run;
        run += local[i];
    }
    if (tid == 255) g_off[NTOT] = run;
}

__global__ void fill_kernel(const int* __restrict__ ei) {
    int e = blockIdx.x * blockDim.x + threadIdx.x;
    if (e < Ee) {
        int d = ei[Ee + e];
        int p = atomicAdd(&g_cur[d], 1);
        g_csr[p] = ei[e];
    } else if (e < EFULL) {
        int v = e - Ee;                 // self loop
        int p = atomicAdd(&g_cur[v], 1);
        g_csr[p] = v;
    }
}

// ---------------- generic NT GEMM: C[m,n] = sum_k A[m,k]*B[n,k] (+A2@B2t)(+Cadd)(+bias) ----------------
__device__ __forceinline__ void gemm_tiles(const float* __restrict__ Ap, const float* __restrict__ Bp,
                                           int Kp, int rowBase, int colBase, int tid, int tx, int ty,
                                           float (&As)[16][68], float (&Bs)[16][132], float (&acc)[4][8]) {
    for (int k0 = 0; k0 < Kp; k0 += 16) {
        {
            int r = tid >> 2;
            int c = (tid & 3) * 4;
            float4 av = *(const float4*)(Ap + (size_t)(rowBase + r) * Kp + k0 + c);
            As[c + 0][r] = av.x; As[c + 1][r] = av.y; As[c + 2][r] = av.z; As[c + 3][r] = av.w;
        }
#pragma unroll
        for (int rr = 0; rr < 2; rr++) {
            int r = (tid >> 2) + rr * 64;
            int c = (tid & 3) * 4;
            float4 bv = *(const float4*)(Bp + (size_t)(colBase + r) * Kp + k0 + c);
            Bs[c + 0][r] = bv.x; Bs[c + 1][r] = bv.y; Bs[c + 2][r] = bv.z; Bs[c + 3][r] = bv.w;
        }
        __syncthreads();
#pragma unroll
        for (int kk = 0; kk < 16; kk++) {
            float4 a  = *(const float4*)&As[kk][ty * 4];
            float4 b0 = *(const float4*)&Bs[kk][tx * 8];
            float4 b1 = *(const float4*)&Bs[kk][tx * 8 + 4];
            float av[4] = {a.x, a.y, a.z, a.w};
            float bv[8] = {b0.x, b0.y, b0.z, b0.w, b1.x, b1.y, b1.z, b1.w};
#pragma unroll
            for (int i = 0; i < 4; i++)
#pragma unroll
                for (int j = 0; j < 8; j++) acc[i][j] += av[i] * bv[j];
        }
        __syncthreads();
    }
}

__global__ __launch_bounds__(256) void gemm_nt(
    const float* __restrict__ A, const float* __restrict__ B, int K,
    const float* __restrict__ A2, const float* __restrict__ B2, int K2,
    const float* __restrict__ Cadd, const float* __restrict__ bias,
    float* __restrict__ C, int N)
{
    __shared__ float As[16][68];
    __shared__ float Bs[16][132];
    float acc[4][8];
#pragma unroll
    for (int i = 0; i < 4; i++)
#pragma unroll
        for (int j = 0; j < 8; j++) acc[i][j] = 0.f;

    const int tid = threadIdx.x;
    const int tx = tid & 15, ty = tid >> 4;
    const int rowBase = blockIdx.y * 64;
    const int colBase = blockIdx.x * 128;

    gemm_tiles(A, B, K, rowBase, colBase, tid, tx, ty, As, Bs, acc);
    if (A2) gemm_tiles(A2, B2, K2, rowBase, colBase, tid, tx, ty, As, Bs, acc);

#pragma unroll
    for (int i = 0; i < 4; i++) {
        int m = rowBase + ty * 4 + i;
#pragma unroll
        for (int j = 0; j < 8; j++) {
            int n = colBase + tx * 8 + j;
            float v = acc[i][j];
            if (bias) v += bias[n];
            if (Cadd) v += Cadd[(size_t)m * N + n];
            C[(size_t)m * N + n] = v;
        }
    }
}

// ---------------- per-head attention logits ----------------
__global__ void att_kernel(const float* __restrict__ att_src, const float* __restrict__ att_dst) {
    int gw   = (blockIdx.x * blockDim.x + threadIdx.x) >> 5;
    int lane = threadIdx.x & 31;
    if (gw >= MTOT) return;
    const float* hr = g_h + (size_t)gw * 128;
    float ps[4], pd[4];
#pragma unroll
    for (int j = 0; j < 4; j++) {
        float hv = hr[j * 32 + lane];
        ps[j] = hv * att_src[j * 32 + lane];
        pd[j] = hv * att_dst[j * 32 + lane];
    }
#pragma unroll
    for (int off = 16; off; off >>= 1)
#pragma unroll
        for (int j = 0; j < 4; j++) {
            ps[j] += __shfl_xor_sync(0xffffffffu, ps[j], off);
            pd[j] += __shfl_xor_sync(0xffffffffu, pd[j], off);
        }
    if (lane == 0)
#pragma unroll
        for (int j = 0; j < 4; j++) {
            g_asrc[gw * 4 + j] = ps[j];
            g_adst[gw * 4 + j] = pd[j];
        }
}

// ---------------- GAT edge softmax + aggregation (warp per (node,t)) ----------------
__global__ void gat_kernel(const float* __restrict__ gat_bias) {
    int warp = threadIdx.x >> 5;
    int lane = threadIdx.x & 31;
    int node = blockIdx.x * 8 + warp;
    int t    = blockIdx.y;
    int beg  = g_off[node], end = g_off[node + 1];

    float ad[4];
#pragma unroll
    for (int j = 0; j < 4; j++) ad[j] = g_adst[(t * NTOT + node) * 4 + j];

    float mx[4] = {-1e30f, -1e30f, -1e30f, -1e30f};
    for (int e = beg + lane; e < end; e += 32) {
        int s = g_csr[e];
        const float* as = g_asrc + (t * NTOT + s) * 4;
#pragma unroll
        for (int j = 0; j < 4; j++) {
            float v = as[j] + ad[j];
            v = v > 0.f ? v : 0.2f * v;
            mx[j] = fmaxf(mx[j], v);
        }
    }
#pragma unroll
    for (int off = 16; off; off >>= 1)
#pragma unroll
        for (int j = 0; j < 4; j++) mx[j] = fmaxf(mx[j], __shfl_xor_sync(0xffffffffu, mx[j], off));

    float den[4] = {0.f, 0.f, 0.f, 0.f};
    for (int e = beg + lane; e < end; e += 32) {
        int s = g_csr[e];
        const float* as = g_asrc + (t * NTOT + s) * 4;
#pragma unroll
        for (int j = 0; j < 4; j++) {
            float v = as[j] + ad[j];
            v = v > 0.f ? v : 0.2f * v;
            den[j] += __expf(v - mx[j]);
        }
    }
#pragma unroll
    for (int off = 16; off; off >>= 1)
#pragma unroll
        for (int j = 0; j < 4; j++) den[j] += __shfl_xor_sync(0xffffffffu, den[j], off);

    float rden[4];
#pragma unroll
    for (int j = 0; j < 4; j++) rden[j] = 1.f / den[j];

    float acc[4] = {0.f, 0.f, 0.f, 0.f};
    for (int e = beg; e < end; e++) {           // whole warp walks edges together
        int s = g_csr[e];
        const float* as = g_asrc + (t * NTOT + s) * 4;
        const float* hs = g_h + (size_t)(t * NTOT + s) * 128;
#pragma unroll
        for (int j = 0; j < 4; j++) {
            float v = as[j] + ad[j];
            v = v > 0.f ? v : 0.2f * v;
            float w = __expf(v - mx[j]) * rden[j];
            acc[j] += w * hs[j * 32 + lane];
        }
    }
#pragma unroll
    for (int j = 0; j < 4; j++) {
        int d = j * 32 + lane;
        float r = acc[j] + gat_bias[d];
        g_spatial[(size_t)(t * NTOT + node) * 128 + d] = fmaxf(r, 0.f);
    }
}

// ---------------- LSTM gate elementwise ----------------
__device__ __forceinline__ float sigmoidf(float x) { return 1.f / (1.f + expf(-x)); }

__global__ void lstm_elem(const float* __restrict__ gates, float* __restrict__ h, float* __restrict__ c) {
    int idx = blockIdx.x * blockDim.x + threadIdx.x;
    if (idx >= NTOT * Hh) return;
    int m = idx >> 7, d = idx & 127;
    const float* g = gates + (size_t)m * 512;
    float si = sigmoidf(g[d]);
    float sf = sigmoidf(g[128 + d]);
    float tg = tanhf(g[256 + d]);
    float so = sigmoidf(g[384 + d]);
    float cn = sf * c[idx] + si * tg;
    c[idx] = cn;
    h[idx] = so * tanhf(cn);
}

// ---------------- LayerNorm ----------------
__global__ void ln_kernel(const float* __restrict__ gamma, const float* __restrict__ beta,
                          float* __restrict__ out) {
    int gw   = (blockIdx.x * blockDim.x + threadIdx.x) >> 5;
    int lane = threadIdx.x & 31;
    if (gw >= NTOT) return;
    const float* hr = g_h1 + (size_t)gw * 128;
    float v[4];
    float s = 0.f, ss = 0.f;
#pragma unroll
    for (int j = 0; j < 4; j++) {
        v[j] = hr[j * 32 + lane];
        s += v[j];
        ss += v[j] * v[j];
    }
#pragma unroll
    for (int off = 16; off; off >>= 1) {
        s  += __shfl_xor_sync(0xffffffffu, s, off);
        ss += __shfl_xor_sync(0xffffffffu, ss, off);
    }
    float mu   = s * (1.f / 128.f);
    float var  = ss * (1.f / 128.f) - mu * mu;
    float rstd = rsqrtf(var + 1e-5f);
#pragma unroll
    for (int j = 0; j < 4; j++) {
        int d = j * 32 + lane;
        out[(size_t)gw * 128 + d] = (v[j] - mu) * rstd * gamma[d] + beta[d];
    }
}

// ---------------- launch ----------------
static float* sym_f(const void* sym) { void* p = nullptr; cudaGetSymbolAddress(&p, sym); return (float*)p; }

extern "C" void kernel_launch(void* const* d_in, const int* in_sizes, int n_in,
                              void* d_out, int out_size) {
    const float* x        = (const float*)d_in[0];
    const float* W        = (const float*)d_in[1];
    const float* att_src  = (const float*)d_in[2];
    const float* att_dst  = (const float*)d_in[3];
    const float* gat_bias = (const float*)d_in[4];
    const float* W_ih0    = (const float*)d_in[5];
    const float* W_hh0    = (const float*)d_in[6];
    const float* b_ih0    = (const float*)d_in[7];
    const float* b_hh0    = (const float*)d_in[8];
    const float* W_ih1    = (const float*)d_in[9];
    const float* W_hh1    = (const float*)d_in[10];
    const float* b_ih1    = (const float*)d_in[11];
    const float* b_hh1    = (const float*)d_in[12];
    const float* ln_gamma = (const float*)d_in[13];
    const float* ln_beta  = (const float*)d_in[14];
    const int*   edge_index = (const int*)d_in[15];
    float* out = (float*)d_out;

    float* p_xflat  = sym_f(g_xflat);
    float* p_Wt     = sym_f(g_Wt);
    float* p_h      = sym_f(g_h);
    float* p_spatial= sym_f(g_spatial);
    float* p_gih0   = sym_f(g_gih0);
    float* p_gates  = sym_f(g_gates);
    float* p_h0     = sym_f(g_h0);
    float* p_c0     = sym_f(g_c0);
    float* p_h1     = sym_f(g_h1);
    float* p_c1     = sym_f(g_c1);
    float* p_bsum0  = sym_f(g_bsum0);
    float* p_bsum1  = sym_f(g_bsum1);

    transpose_x<<<(MTOT * Ff + 255) / 256, 256>>>(x);
    wt_kernel<<<(Hh * Ff + 255) / 256, 256>>>(W);
    init_kernel<<<(NTOT + 255) / 256, 256>>>(b_ih0, b_hh0, b_ih1, b_hh1);
    zero_state<<<(NTOT * Hh + 255) / 256, 256>>>();
    count_kernel<<<(Ee + 255) / 256, 256>>>(edge_index);
    scan_kernel<<<1, 256>>>();
    fill_kernel<<<(EFULL + 255) / 256, 256>>>(edge_index);

    // h = x_flat @ W   (M=81920, N=128, K=64)
    gemm_nt<<<dim3(1, MTOT / 64), 256>>>(p_xflat, p_Wt, Ff,
                                         nullptr, nullptr, 0, nullptr, nullptr, p_h, Hh);
    att_kernel<<<(MTOT * 32 + 255) / 256, 256>>>(att_src, att_dst);
    gat_kernel<<<dim3(NTOT / 8, Tt), 256>>>(gat_bias);

    // precompute layer-0 input gates for all timesteps: spatial @ W_ih0^T + (b_ih0+b_hh0)
    gemm_nt<<<dim3(4, MTOT / 64), 256>>>(p_spatial, W_ih0, Hh,
                                         nullptr, nullptr, 0, nullptr, p_bsum0, p_gih0, G4H);

    for (int t = 0; t < Tt; t++) {
        // layer 0: gates = gih0[t] + h0 @ W_hh0^T
        gemm_nt<<<dim3(4, NTOT / 64), 256>>>(p_h0, W_hh0, Hh,
                                             nullptr, nullptr, 0,
                                             p_gih0 + (size_t)t * NTOT * G4H, nullptr, p_gates, G4H);
        lstm_elem<<<(NTOT * Hh + 255) / 256, 256>>>(p_gates, p_h0, p_c0);
        // layer 1: gates = h0 @ W_ih1^T + h1 @ W_hh1^T + (b_ih1+b_hh1)
        gemm_nt<<<dim3(4, NTOT / 64), 256>>>(p_h0, W_ih1, Hh,
                                             p_h1, W_hh1, Hh,
                                             nullptr, p_bsum1, p_gates, G4H);
        lstm_elem<<<(NTOT * Hh + 255) / 256, 256>>>(p_gates, p_h1, p_c1);
    }

    ln_kernel<<<(NTOT * 32 + 255) / 256, 256>>>(ln_gamma, ln_beta, out);
}

// round 4
// speedup vs baseline: 2.3489x; 2.3489x over previous
#include <cuda_runtime.h>
#include <cuda_fp16.h>
#include <math.h>
#include <stdint.h>

#define Bb    4
#define Tt    10
#define Nn    2048
#define Ff    64
#define Hh    128
#define NHEAD 4
#define Dd    32
#define Ee    65536
#define NTOT  8192            // B*N
#define MTOT  81920           // T*NTOT
#define G4H   512             // 4*H
#define EFULL (Ee + NTOT)     // edges + self loops

// ---------------- device scratch (no allocations allowed) ----------------
__device__ float g_xflat[MTOT * Ff];
__device__ float g_Wt[Hh * Ff];
__device__ float g_h[MTOT * Hh];
__device__ float g_asrc[MTOT * NHEAD];
__device__ float g_adst[MTOT * NHEAD];
__device__ float g_spatial[MTOT * Hh];
__device__ float g_gates[NTOT * G4H];
__device__ float g_h0[NTOT * Hh];
__device__ float g_c0[NTOT * Hh];
__device__ float g_h1[NTOT * Hh];
__device__ float g_c1[NTOT * Hh];
__device__ float g_bsum0[G4H];
__device__ float g_bsum1[G4H];
__device__ int   g_count[NTOT];
__device__ int   g_off[NTOT + 1];
__device__ int   g_cur[NTOT];
__device__ int   g_csr[EFULL];

// ============================ warp-MMA fp16x3 GEMM ============================
// C[m,n] = sum_k A[m,k]*B[n,k] (+ A2@B2^T) (+bias).
// fp32 operands split hi/lo fp16; 3 MMAs (hi*hi + hi*lo + lo*hi) per fragment
// give ~22-bit effective mantissa. Block tile 128x128, warp tile 64x32, kc=32.

#define KC        32
#define LDS_ROW   40          // halfs per SMEM row (80B, conflict-free ldmatrix)

__device__ __forceinline__ uint32_t smem_u32(const void* p) {
    return (uint32_t)__cvta_generic_to_shared(p);
}

__device__ __forceinline__ void ldsm_x4(uint32_t (&r)[4], uint32_t addr) {
    asm volatile("ldmatrix.sync.aligned.m8n8.x4.shared.b16 {%0,%1,%2,%3}, [%4];"
                 : "=r"(r[0]), "=r"(r[1]), "=r"(r[2]), "=r"(r[3]) : "r"(addr));
}
__device__ __forceinline__ void ldsm_x2(uint32_t (&r)[2], uint32_t addr) {
    asm volatile("ldmatrix.sync.aligned.m8n8.x2.shared.b16 {%0,%1}, [%2];"
                 : "=r"(r[0]), "=r"(r[1]) : "r"(addr));
}
__device__ __forceinline__ void mma16816(float (&c)[4], const uint32_t (&a)[4], const uint32_t (&b)[2]) {
    asm volatile("mma.sync.aligned.m16n8k16.row.col.f32.f16.f16.f32 "
                 "{%0,%1,%2,%3}, {%4,%5,%6,%7}, {%8,%9}, {%0,%1,%2,%3};"
                 : "+f"(c[0]), "+f"(c[1]), "+f"(c[2]), "+f"(c[3])
                 : "r"(a[0]), "r"(a[1]), "r"(a[2]), "r"(a[3]), "r"(b[0]), "r"(b[1]));
}

__device__ __forceinline__ void split_store(__half* hi_s, __half* lo_s, int idx, float x, float y) {
    __half2 h = __floats2half2_rn(x, y);
    float2 back = __half22float2(h);
    __half2 l = __floats2half2_rn(x - back.x, y - back.y);
    *(uint32_t*)(hi_s + idx) = *(uint32_t*)&h;
    *(uint32_t*)(lo_s + idx) = *(uint32_t*)&l;
}

__global__ __launch_bounds__(256) void gemm_wm(
    const float* __restrict__ A,  const float* __restrict__ B,  int K,
    const float* __restrict__ A2, const float* __restrict__ B2, int K2,
    const float* __restrict__ bias, float* __restrict__ C, int ldC)
{
    __shared__ __half Ahi_s[128 * LDS_ROW];
    __shared__ __half Alo_s[128 * LDS_ROW];
    __shared__ __half Bhi_s[128 * LDS_ROW];
    __shared__ __half Blo_s[128 * LDS_ROW];

    const int tid  = threadIdx.x;
    const int wid  = tid >> 5;
    const int lane = tid & 31;
    const int mBase   = blockIdx.y * 128;
    const int colBase = blockIdx.x * 128;
    const int warpM = (wid >> 2) * 64;   // 0 or 64
    const int warpN = (wid & 3) * 32;    // 0,32,64,96

    // fill mapping: each thread handles one half-row of 16 floats
    const int fRow = tid >> 1;
    const int fCol = (tid & 1) * 16;

    // ldmatrix lane-address components
    const int rowA_sel = lane & 15;
    const int colA8    = (lane >> 4) * 8;
    const int rowB_sel = lane & 7;
    const int colB8    = ((lane >> 3) & 1) * 8;

    float acc[4][4][4];
#pragma unroll
    for (int i = 0; i < 4; i++)
#pragma unroll
        for (int j = 0; j < 4; j++)
#pragma unroll
            for (int q = 0; q < 4; q++) acc[i][j][q] = 0.f;

    const uint32_t ahi_b = smem_u32(Ahi_s), alo_b = smem_u32(Alo_s);
    const uint32_t bhi_b = smem_u32(Bhi_s), blo_b = smem_u32(Blo_s);

    for (int pair = 0; pair < 2; pair++) {
        const float* Ap = pair ? A2 : A;
        const float* Bp = pair ? B2 : B;
        const int    Kp = pair ? K2 : K;
        if (!Ap) continue;

        for (int k0 = 0; k0 < Kp; k0 += KC) {
            // ---- fill A/B chunks with hi/lo split ----
            {
                const float* ar = Ap + (size_t)(mBase + fRow) * Kp + k0 + fCol;
                const float* br = Bp + (size_t)(colBase + fRow) * Kp + k0 + fCol;
                int sidx = fRow * LDS_ROW + fCol;
#pragma unroll
                for (int v = 0; v < 4; v++) {
                    float4 av = *(const float4*)(ar + v * 4);
                    split_store(Ahi_s, Alo_s, sidx + v * 4 + 0, av.x, av.y);
                    split_store(Ahi_s, Alo_s, sidx + v * 4 + 2, av.z, av.w);
                    float4 bv = *(const float4*)(br + v * 4);
                    split_store(Bhi_s, Blo_s, sidx + v * 4 + 0, bv.x, bv.y);
                    split_store(Bhi_s, Blo_s, sidx + v * 4 + 2, bv.z, bv.w);
                }
            }
            __syncthreads();

#pragma unroll
            for (int ks = 0; ks < KC / 16; ks++) {
                uint32_t ahi[4][4], alo[4][4], bhi[4][2], blo[4][2];
#pragma unroll
                for (int mi = 0; mi < 4; mi++) {
                    uint32_t off = (uint32_t)(((warpM + mi * 16 + rowA_sel) * LDS_ROW + ks * 16 + colA8) * 2);
                    ldsm_x4(ahi[mi], ahi_b + off);
                    ldsm_x4(alo[mi], alo_b + off);
                }
#pragma unroll
                for (int ni = 0; ni < 4; ni++) {
                    uint32_t off = (uint32_t)(((warpN + ni * 8 + rowB_sel) * LDS_ROW + ks * 16 + colB8) * 2);
                    ldsm_x2(bhi[ni], bhi_b + off);
                    ldsm_x2(blo[ni], blo_b + off);
                }
#pragma unroll
                for (int mi = 0; mi < 4; mi++)
#pragma unroll
                    for (int ni = 0; ni < 4; ni++) {
                        mma16816(acc[mi][ni], ahi[mi], bhi[ni]);
                        mma16816(acc[mi][ni], ahi[mi], blo[ni]);
                        mma16816(acc[mi][ni], alo[mi], bhi[ni]);
                    }
            }
            __syncthreads();
        }
    }

    // ---- epilogue ----
    const int g = lane >> 2, t4 = lane & 3;
#pragma unroll
    for (int mi = 0; mi < 4; mi++) {
        int m0 = mBase + warpM + mi * 16 + g;
#pragma unroll
        for (int ni = 0; ni < 4; ni++) {
            int n = colBase + warpN + ni * 8 + t4 * 2;
            float b0 = 0.f, b1 = 0.f;
            if (bias) { b0 = bias[n]; b1 = bias[n + 1]; }
            float2 v0 = make_float2(acc[mi][ni][0] + b0, acc[mi][ni][1] + b1);
            float2 v1 = make_float2(acc[mi][ni][2] + b0, acc[mi][ni][3] + b1);
            *(float2*)(C + (size_t)m0 * ldC + n) = v0;
            *(float2*)(C + (size_t)(m0 + 8) * ldC + n) = v1;
        }
    }
}

// ---------------- small prep kernels ----------------
__global__ void transpose_x(const float* __restrict__ x) {
    int idx = blockIdx.x * blockDim.x + threadIdx.x;
    if (idx >= MTOT * Ff) return;
    int f  = idx & 63;
    int r  = idx >> 6;        // m = (t*B + b)*N + n
    int n  = r & (Nn - 1);
    int bt = r >> 11;         // t*B + b
    int b  = bt & 3;
    int t  = bt >> 2;
    g_xflat[idx] = x[(((size_t)(b * Tt + t) * Nn + n) << 6) + f];
}

__global__ void wt_kernel(const float* __restrict__ W) {
    int i = blockIdx.x * blockDim.x + threadIdx.x;
    if (i >= Hh * Ff) return;
    int n = i >> 6, k = i & 63;
    g_Wt[i] = W[k * Hh + n];   // Wt[n][k] = W[k][n]
}

__global__ void init_kernel(const float* __restrict__ b_ih0, const float* __restrict__ b_hh0,
                            const float* __restrict__ b_ih1, const float* __restrict__ b_hh1) {
    int i = blockIdx.x * blockDim.x + threadIdx.x;
    if (i < NTOT) g_count[i] = 1;  // self loop pre-counted
    if (i < G4H) {
        g_bsum0[i] = b_ih0[i] + b_hh0[i];
        g_bsum1[i] = b_ih1[i] + b_hh1[i];
    }
}

__global__ void zero_state() {
    int i = blockIdx.x * blockDim.x + threadIdx.x;
    if (i >= NTOT * Hh) return;
    g_h0[i] = 0.f; g_c0[i] = 0.f; g_h1[i] = 0.f; g_c1[i] = 0.f;
}

__global__ void count_kernel(const int* __restrict__ ei) {
    int e = blockIdx.x * blockDim.x + threadIdx.x;
    if (e < Ee) atomicAdd(&g_count[ei[Ee + e]], 1);
}

__global__ void scan_kernel() {
    __shared__ int part[256];
    int tid  = threadIdx.x;
    int base = tid * 32;
    int local[32];
    int s = 0;
#pragma unroll
    for (int i = 0; i < 32; i++) { local[i] = g_count[base + i]; s += local[i]; }
    part[tid] = s;
    __syncthreads();
    for (int off = 1; off < 256; off <<= 1) {
        int v = (tid >= off) ? part[tid - off] : 0;
        __syncthreads();
        part[tid] += v;
        __syncthreads();
    }
    int run = part[tid] - s;
#pragma unroll
    for (int i = 0; i < 32; i++) {
        g_off[base + i] = run;
        g_cur[base + i] = run;
        run += local[i];
    }
    if (tid == 255) g_off[NTOT] = run;
}

__global__ void fill_kernel(const int* __restrict__ ei) {
    int e = blockIdx.x * blockDim.x + threadIdx.x;
    if (e < Ee) {
        int d = ei[Ee + e];
        int p = atomicAdd(&g_cur[d], 1);
        g_csr[p] = ei[e];
    } else if (e < EFULL) {
        int v = e - Ee;
        int p = atomicAdd(&g_cur[v], 1);
        g_csr[p] = v;
    }
}

// ---------------- per-head attention logits ----------------
__global__ void att_kernel(const float* __restrict__ att_src, const float* __restrict__ att_dst) {
    int gw   = (blockIdx.x * blockDim.x + threadIdx.x) >> 5;
    int lane = threadIdx.x & 31;
    if (gw >= MTOT) return;
    const float* hr = g_h + (size_t)gw * 128;
    float ps[4], pd[4];
#pragma unroll
    for (int j = 0; j < 4; j++) {
        float hv = hr[j * 32 + lane];
        ps[j] = hv * att_src[j * 32 + lane];
        pd[j] = hv * att_dst[j * 32 + lane];
    }
#pragma unroll
    for (int off = 16; off; off >>= 1)
#pragma unroll
        for (int j = 0; j < 4; j++) {
            ps[j] += __shfl_xor_sync(0xffffffffu, ps[j], off);
            pd[j] += __shfl_xor_sync(0xffffffffu, pd[j], off);
        }
    if (lane == 0)
#pragma unroll
        for (int j = 0; j < 4; j++) {
            g_asrc[gw * 4 + j] = ps[j];
            g_adst[gw * 4 + j] = pd[j];
        }
}

// ---------------- GAT edge softmax + aggregation (warp per (node,t)) ----------------
__global__ void gat_kernel(const float* __restrict__ gat_bias) {
    int warp = threadIdx.x >> 5;
    int lane = threadIdx.x & 31;
    int node = blockIdx.x * 8 + warp;
    int t    = blockIdx.y;
    int beg  = g_off[node], end = g_off[node + 1];

    float ad[4];
#pragma unroll
    for (int j = 0; j < 4; j++) ad[j] = g_adst[(t * NTOT + node) * 4 + j];

    float mx[4] = {-1e30f, -1e30f, -1e30f, -1e30f};
    for (int e = beg + lane; e < end; e += 32) {
        int s = g_csr[e];
        const float* as = g_asrc + (t * NTOT + s) * 4;
#pragma unroll
        for (int j = 0; j < 4; j++) {
            float v = as[j] + ad[j];
            v = v > 0.f ? v : 0.2f * v;
            mx[j] = fmaxf(mx[j], v);
        }
    }
#pragma unroll
    for (int off = 16; off; off >>= 1)
#pragma unroll
        for (int j = 0; j < 4; j++) mx[j] = fmaxf(mx[j], __shfl_xor_sync(0xffffffffu, mx[j], off));

    float den[4] = {0.f, 0.f, 0.f, 0.f};
    for (int e = beg + lane; e < end; e += 32) {
        int s = g_csr[e];
        const float* as = g_asrc + (t * NTOT + s) * 4;
#pragma unroll
        for (int j = 0; j < 4; j++) {
            float v = as[j] + ad[j];
            v = v > 0.f ? v : 0.2f * v;
            den[j] += __expf(v - mx[j]);
        }
    }
#pragma unroll
    for (int off = 16; off; off >>= 1)
#pragma unroll
        for (int j = 0; j < 4; j++) den[j] += __shfl_xor_sync(0xffffffffu, den[j], off);

    float rden[4];
#pragma unroll
    for (int j = 0; j < 4; j++) rden[j] = 1.f / den[j];

    float acc[4] = {0.f, 0.f, 0.f, 0.f};
    for (int e = beg; e < end; e++) {
        int s = g_csr[e];
        const float* as = g_asrc + (t * NTOT + s) * 4;
        const float* hs = g_h + (size_t)(t * NTOT + s) * 128;
#pragma unroll
        for (int j = 0; j < 4; j++) {
            float v = as[j] + ad[j];
            v = v > 0.f ? v : 0.2f * v;
            float w = __expf(v - mx[j]) * rden[j];
            acc[j] += w * hs[j * 32 + lane];
        }
    }
#pragma unroll
    for (int j = 0; j < 4; j++) {
        int d = j * 32 + lane;
        float r = acc[j] + gat_bias[d];
        g_spatial[(size_t)(t * NTOT + node) * 128 + d] = fmaxf(r, 0.f);
    }
}

// ---------------- LSTM gate elementwise ----------------
__device__ __forceinline__ float sigmoidf(float x) { return 1.f / (1.f + expf(-x)); }

__global__ void lstm_elem(const float* __restrict__ gates, float* __restrict__ h, float* __restrict__ c) {
    int idx = blockIdx.x * blockDim.x + threadIdx.x;
    if (idx >= NTOT * Hh) return;
    int m = idx >> 7, d = idx & 127;
    const float* g = gates + (size_t)m * 512;
    float si = sigmoidf(g[d]);
    float sf = sigmoidf(g[128 + d]);
    float tg = tanhf(g[256 + d]);
    float so = sigmoidf(g[384 + d]);
    float cn = sf * c[idx] + si * tg;
    c[idx] = cn;
    h[idx] = so * tanhf(cn);
}

// ---------------- LayerNorm ----------------
__global__ void ln_kernel(const float* __restrict__ gamma, const float* __restrict__ beta,
                          float* __restrict__ out) {
    int gw   = (blockIdx.x * blockDim.x + threadIdx.x) >> 5;
    int lane = threadIdx.x & 31;
    if (gw >= NTOT) return;
    const float* hr = g_h1 + (size_t)gw * 128;
    float v[4];
    float s = 0.f, ss = 0.f;
#pragma unroll
    for (int j = 0; j < 4; j++) {
        v[j] = hr[j * 32 + lane];
        s += v[j];
        ss += v[j] * v[j];
    }
#pragma unroll
    for (int off = 16; off; off >>= 1) {
        s  += __shfl_xor_sync(0xffffffffu, s, off);
        ss += __shfl_xor_sync(0xffffffffu, ss, off);
    }
    float mu   = s * (1.f / 128.f);
    float var  = ss * (1.f / 128.f) - mu * mu;
    float rstd = rsqrtf(var + 1e-5f);
#pragma unroll
    for (int j = 0; j < 4; j++) {
        int d = j * 32 + lane;
        out[(size_t)gw * 128 + d] = (v[j] - mu) * rstd * gamma[d] + beta[d];
    }
}

// ---------------- launch ----------------
static float* sym_f(const void* sym) { void* p = nullptr; cudaGetSymbolAddress(&p, sym); return (float*)p; }

extern "C" void kernel_launch(void* const* d_in, const int* in_sizes, int n_in,
                              void* d_out, int out_size) {
    const float* x        = (const float*)d_in[0];
    const float* W        = (const float*)d_in[1];
    const float* att_src  = (const float*)d_in[2];
    const float* att_dst  = (const float*)d_in[3];
    const float* gat_bias = (const float*)d_in[4];
    const float* W_ih0    = (const float*)d_in[5];
    const float* W_hh0    = (const float*)d_in[6];
    const float* b_ih0    = (const float*)d_in[7];
    const float* b_hh0    = (const float*)d_in[8];
    const float* W_ih1    = (const float*)d_in[9];
    const float* W_hh1    = (const float*)d_in[10];
    const float* b_ih1    = (const float*)d_in[11];
    const float* b_hh1    = (const float*)d_in[12];
    const float* ln_gamma = (const float*)d_in[13];
    const float* ln_beta  = (const float*)d_in[14];
    const int*   edge_index = (const int*)d_in[15];
    float* out = (float*)d_out;

    float* p_xflat  = sym_f(g_xflat);
    float* p_Wt     = sym_f(g_Wt);
    float* p_h      = sym_f(g_h);
    float* p_spatial= sym_f(g_spatial);
    float* p_gates  = sym_f(g_gates);
    float* p_h0     = sym_f(g_h0);
    float* p_c0     = sym_f(g_c0);
    float* p_h1     = sym_f(g_h1);
    float* p_c1     = sym_f(g_c1);
    float* p_bsum0  = sym_f(g_bsum0);
    float* p_bsum1  = sym_f(g_bsum1);

    transpose_x<<<(MTOT * Ff + 255) / 256, 256>>>(x);
    wt_kernel<<<(Hh * Ff + 255) / 256, 256>>>(W);
    init_kernel<<<(NTOT + 255) / 256, 256>>>(b_ih0, b_hh0, b_ih1, b_hh1);
    zero_state<<<(NTOT * Hh + 255) / 256, 256>>>();
    count_kernel<<<(Ee + 255) / 256, 256>>>(edge_index);
    scan_kernel<<<1, 256>>>();
    fill_kernel<<<(EFULL + 255) / 256, 256>>>(edge_index);

    // h = x_flat @ Wt^T   (M=81920, N=128, K=64)
    gemm_wm<<<dim3(1, MTOT / 128), 256>>>(
        p_xflat, p_Wt, Ff, nullptr, nullptr, 0, nullptr, p_h, Hh);

    att_kernel<<<(MTOT * 32 + 255) / 256, 256>>>(att_src, att_dst);
    gat_kernel<<<dim3(NTOT / 8, Tt), 256>>>(gat_bias);

    for (int t = 0; t < Tt; t++) {
        // layer 0: gates = spatial[t] @ W_ih0^T + h0 @ W_hh0^T + (b_ih0+b_hh0)
        gemm_wm<<<dim3(4, NTOT / 128), 256>>>(
            p_spatial + (size_t)t * NTOT * Hh, W_ih0, Hh,
            p_h0, W_hh0, Hh, p_bsum0, p_gates, G4H);
        lstm_elem<<<(NTOT * Hh + 255) / 256, 256>>>(p_gates, p_h0, p_c0);
        // layer 1: gates = h0 @ W_ih1^T + h1 @ W_hh1^T + (b_ih1+b_hh1)
        gemm_wm<<<dim3(4, NTOT / 128), 256>>>(
            p_h0, W_ih1, Hh, p_h1, W_hh1, Hh, p_bsum1, p_gates, G4H);
        lstm_elem<<<(NTOT * Hh + 255) / 256, 256>>>(p_gates, p_h1, p_c1);
    }

    ln_kernel<<<(NTOT * 32 + 255) / 256, 256>>>(ln_gamma, ln_beta, out);
}

// round 7
// speedup vs baseline: 2.7494x; 1.1705x over previous
#include <cuda_runtime.h>
#include <cuda_fp16.h>
#include <math.h>
#include <stdint.h>

#define Bb    4
#define Tt    10
#define Nn    2048
#define Ff    64
#define Hh    128
#define NHEAD 4
#define Dd    32
#define Ee    65536
#define NTOT  8192            // B*N
#define MTOT  81920           // T*NTOT
#define G4H   512             // 4*H
#define EFULL (Ee + NTOT)     // edges + self loops

// ---------------- device scratch (no allocations allowed) ----------------
// fp16 hi/lo split operands (produced once, consumed by GEMMs)
__device__ __align__(16) __half g_xhi[MTOT * Ff],  g_xlo[MTOT * Ff];
__device__ __align__(16) __half g_wthi[Hh * Ff],   g_wtlo[Hh * Ff];
__device__ __align__(16) __half g_sphi[MTOT * Hh], g_splo[MTOT * Hh];
__device__ __align__(16) __half g_w0hi[G4H * Hh],  g_w0lo[G4H * Hh];   // W_ih0
__device__ __align__(16) __half g_u0hi[G4H * Hh],  g_u0lo[G4H * Hh];   // W_hh0
__device__ __align__(16) __half g_w1hi[G4H * Hh],  g_w1lo[G4H * Hh];   // W_ih1
__device__ __align__(16) __half g_u1hi[G4H * Hh],  g_u1lo[G4H * Hh];   // W_hh1
__device__ __align__(16) __half g_h0hi[NTOT * Hh], g_h0lo[NTOT * Hh];
__device__ __align__(16) __half g_h1hi[NTOT * Hh], g_h1lo[NTOT * Hh];

__device__ float g_h[MTOT * Hh];        // GAT projections (fp32, read by att/gat)
__device__ float g_gates[NTOT * G4H];
__device__ float g_c0[NTOT * Hh];
__device__ float g_c1[NTOT * Hh];
__device__ float g_h1f[NTOT * Hh];      // fp32 h1 for LayerNorm
__device__ float g_bsum0[G4H];
__device__ float g_bsum1[G4H];
__device__ int   g_count[NTOT];
__device__ int   g_off[NTOT + 1];
__device__ int   g_cur[NTOT];
__device__ int   g_csr[EFULL];

// ============================ warp-MMA fp16x3 GEMM ============================
// C[m,n] = sum_k A[m,k]*B[n,k] (+ A2@B2^T) (+bias). Operands pre-split hi/lo fp16.
// Block tile 128x128, warp tile 64x32, k-chunk 32, cp.async double-buffered.

#define LDSROW   40                 // halfs per SMEM row (80B, conflict-free ldmatrix)
#define CHUNK_H  (128 * LDSROW)     // halfs per operand-array chunk
#define CH2      (CHUNK_H * 2)      // bytes per operand-array chunk
#define BUFB     (4 * CH2)          // bytes per buffer (4 arrays)

__device__ __forceinline__ uint32_t smem_u32(const void* p) {
    return (uint32_t)__cvta_generic_to_shared(p);
}
__device__ __forceinline__ void cp16(uint32_t dst, const void* src) {
    asm volatile("cp.async.ca.shared.global [%0], [%1], 16;" :: "r"(dst), "l"(src));
}
__device__ __forceinline__ void ldsm_x4(uint32_t (&r)[4], uint32_t addr) {
    asm volatile("ldmatrix.sync.aligned.m8n8.x4.shared.b16 {%0,%1,%2,%3}, [%4];"
                 : "=r"(r[0]), "=r"(r[1]), "=r"(r[2]), "=r"(r[3]) : "r"(addr));
}
__device__ __forceinline__ void mma16816(float (&c)[4], const uint32_t (&a)[4],
                                         uint32_t b0, uint32_t b1) {
    asm volatile("mma.sync.aligned.m16n8k16.row.col.f32.f16.f16.f32 "
                 "{%0,%1,%2,%3}, {%4,%5,%6,%7}, {%8,%9}, {%0,%1,%2,%3};"
                 : "+f"(c[0]), "+f"(c[1]), "+f"(c[2]), "+f"(c[3])
                 : "r"(a[0]), "r"(a[1]), "r"(a[2]), "r"(a[3]), "r"(b0), "r"(b1));
}

__global__ __launch_bounds__(256) void gemm_wm(
    const __half* __restrict__ Ahi,  const __half* __restrict__ Alo,
    const __half* __restrict__ Bhi,  const __half* __restrict__ Blo,  int K,
    const __half* __restrict__ A2hi, const __half* __restrict__ A2lo,
    const __half* __restrict__ B2hi, const __half* __restrict__ B2lo, int K2,
    const float* __restrict__ bias, float* __restrict__ C, int ldC)
{
    extern __shared__ __half sbuf[];   // [2][4][CHUNK_H]
    const uint32_t sb = smem_u32(sbuf);
    const int tid  = threadIdx.x;
    const int wid  = tid >> 5;
    const int lane = tid & 31;
    const int mBase   = blockIdx.y * 128;
    const int colBase = blockIdx.x * 128;
    const int warpM = (wid >> 2) * 64;
    const int warpN = (wid & 3) * 32;

    const int nc1 = K >> 5;
    const int nc2 = A2hi ? (K2 >> 5) : 0;
    const int nc  = nc1 + nc2;

    float acc[4][4][4];
#pragma unroll
    for (int i = 0; i < 4; i++)
#pragma unroll
        for (int j = 0; j < 4; j++)
#pragma unroll
            for (int q = 0; q < 4; q++) acc[i][j][q] = 0.f;

    auto issue = [&](int ci, int bsel) {
        int pair = (ci >= nc1) ? 1 : 0;
        int k0   = ((pair ? (ci - nc1) : ci) << 5);
        int Kp   = pair ? K2 : K;
        const __half* ah = pair ? A2hi : Ahi;
        const __half* al = pair ? A2lo : Alo;
        const __half* bh = pair ? B2hi : Bhi;
        const __half* bl = pair ? B2lo : Blo;
        uint32_t dB = sb + (uint32_t)bsel * BUFB;
#pragma unroll
        for (int j = 0; j < 2; j++) {
            int u = tid * 2 + j, row = u >> 2, seg = u & 3;
            uint32_t so = (uint32_t)((row * LDSROW + seg * 8) * 2);
            size_t aoff = (size_t)(mBase  + row) * Kp + k0 + seg * 8;
            size_t boff = (size_t)(colBase + row) * Kp + k0 + seg * 8;
            cp16(dB + 0 * CH2 + so, ah + aoff);
            cp16(dB + 1 * CH2 + so, al + aoff);
            cp16(dB + 2 * CH2 + so, bh + boff);
            cp16(dB + 3 * CH2 + so, bl + boff);
        }
        asm volatile("cp.async.commit_group;" ::: "memory");
    };

    issue(0, 0);
    for (int ci = 0; ci < nc; ci++) {
        int bsel = ci & 1;
        if (ci + 1 < nc) {
            issue(ci + 1, bsel ^ 1);
            asm volatile("cp.async.wait_group 1;" ::: "memory");
        } else {
            asm volatile("cp.async.wait_group 0;" ::: "memory");
        }
        __syncthreads();

        const uint32_t base = sb + (uint32_t)bsel * BUFB;
        const uint32_t aHiB = base,           aLoB = base + CH2;
        const uint32_t bHiB = base + 2 * CH2, bLoB = base + 3 * CH2;

#pragma unroll
        for (int ks = 0; ks < 2; ks++) {
            uint32_t ahi_f[4][4], alo_f[4][4], bhi_f[2][4], blo_f[2][4];
#pragma unroll
            for (int mi = 0; mi < 4; mi++) {
                uint32_t off = (uint32_t)(((warpM + mi * 16 + (lane & 15)) * LDSROW
                                           + ks * 16 + (lane >> 4) * 8) * 2);
                ldsm_x4(ahi_f[mi], aHiB + off);
                ldsm_x4(alo_f[mi], aLoB + off);
            }
#pragma unroll
            for (int p = 0; p < 2; p++) {
                uint32_t off = (uint32_t)(((warpN + p * 16 + (lane >> 4) * 8 + (lane & 7)) * LDSROW
                                           + ks * 16 + ((lane >> 3) & 1) * 8) * 2);
                ldsm_x4(bhi_f[p], bHiB + off);
                ldsm_x4(blo_f[p], bLoB + off);
            }
#pragma unroll
            for (int mi = 0; mi < 4; mi++)
#pragma unroll
                for (int p = 0; p < 2; p++)
#pragma unroll
                    for (int q = 0; q < 2; q++) {
                        int ni = p * 2 + q;
                        mma16816(acc[mi][ni], ahi_f[mi], bhi_f[p][q * 2], bhi_f[p][q * 2 + 1]);
                        mma16816(acc[mi][ni], ahi_f[mi], blo_f[p][q * 2], blo_f[p][q * 2 + 1]);
                        mma16816(acc[mi][ni], alo_f[mi], bhi_f[p][q * 2], bhi_f[p][q * 2 + 1]);
                    }
        }
        __syncthreads();
    }

    // ---- epilogue ----
    const int g = lane >> 2, t4 = lane & 3;
#pragma unroll
    for (int mi = 0; mi < 4; mi++) {
        int m0 = mBase + warpM + mi * 16 + g;
#pragma unroll
        for (int ni = 0; ni < 4; ni++) {
            int n = colBase + warpN + ni * 8 + t4 * 2;
            float b0 = 0.f, b1 = 0.f;
            if (bias) { b0 = bias[n]; b1 = bias[n + 1]; }
            float2 v0 = make_float2(acc[mi][ni][0] + b0, acc[mi][ni][1] + b1);
            float2 v1 = make_float2(acc[mi][ni][2] + b0, acc[mi][ni][3] + b1);
            *(float2*)(C + (size_t)m0 * ldC + n) = v0;
            *(float2*)(C + (size_t)(m0 + 8) * ldC + n) = v1;
        }
    }
}

// ---------------- split helper ----------------
__device__ __forceinline__ void split_wr(__half* hi, __half* lo, int idx, float v) {
    __half h = __float2half_rn(v);
    hi[idx] = h;
    lo[idx] = __float2half_rn(v - __half2float(h));
}

// ---------------- small prep kernels ----------------
__global__ void transpose_x(const float* __restrict__ x) {
    int idx = blockIdx.x * blockDim.x + threadIdx.x;
    if (idx >= MTOT * Ff) return;
    int f  = idx & 63;
    int r  = idx >> 6;        // m = (t*B + b)*N + n
    int n  = r & (Nn - 1);
    int bt = r >> 11;         // t*B + b
    int b  = bt & 3;
    int t  = bt >> 2;
    float v = x[(((size_t)(b * Tt + t) * Nn + n) << 6) + f];
    split_wr(g_xhi, g_xlo, idx, v);
}

__global__ void wt_kernel(const float* __restrict__ W) {
    int i = blockIdx.x * blockDim.x + threadIdx.x;
    if (i >= Hh * Ff) return;
    int n = i >> 6, k = i & 63;
    split_wr(g_wthi, g_wtlo, i, W[k * Hh + n]);   // Wt[n][k] = W[k][n]
}

__global__ void split_w(const float* __restrict__ w0, const float* __restrict__ u0,
                        const float* __restrict__ w1, const float* __restrict__ u1) {
    int i = blockIdx.x * blockDim.x + threadIdx.x;
    if (i >= 4 * G4H * Hh) return;
    int which = i >> 16;           // G4H*Hh = 65536
    int j = i & 65535;
    if      (which == 0) split_wr(g_w0hi, g_w0lo, j, w0[j]);
    else if (which == 1) split_wr(g_u0hi, g_u0lo, j, u0[j]);
    else if (which == 2) split_wr(g_w1hi, g_w1lo, j, w1[j]);
    else                 split_wr(g_u1hi, g_u1lo, j, u1[j]);
}

__global__ void init_kernel(const float* __restrict__ b_ih0, const float* __restrict__ b_hh0,
                            const float* __restrict__ b_ih1, const float* __restrict__ b_hh1) {
    int i = blockIdx.x * blockDim.x + threadIdx.x;
    if (i < NTOT) g_count[i] = 1;  // self loop pre-counted
    if (i < G4H) {
        g_bsum0[i] = b_ih0[i] + b_hh0[i];
        g_bsum1[i] = b_ih1[i] + b_hh1[i];
    }
}

__global__ void zero_state() {
    int i = blockIdx.x * blockDim.x + threadIdx.x;
    if (i >= NTOT * Hh) return;
    g_c0[i] = 0.f; g_c1[i] = 0.f;
    __half z = __float2half(0.f);
    g_h0hi[i] = z; g_h0lo[i] = z; g_h1hi[i] = z; g_h1lo[i] = z;
}

__global__ void count_kernel(const int* __restrict__ ei) {
    int e = blockIdx.x * blockDim.x + threadIdx.x;
    if (e < Ee) atomicAdd(&g_count[ei[Ee + e]], 1);
}

__global__ void scan_kernel() {
    __shared__ int part[256];
    int tid  = threadIdx.x;
    int base = tid * 32;
    int local[32];
    int s = 0;
#pragma unroll
    for (int i = 0; i < 32; i++) { local[i] = g_count[base + i]; s += local[i]; }
    part[tid] = s;
    __syncthreads();
    for (int off = 1; off < 256; off <<= 1) {
        int v = (tid >= off) ? part[tid - off] : 0;
        __syncthreads();
        part[tid] += v;
        __syncthreads();
    }
    int run = part[tid] - s;
#pragma unroll
    for (int i = 0; i < 32; i++) {
        g_off[base + i] = run;
        g_cur[base + i] = run;
        run += local[i];
    }
    if (tid == 255) g_off[NTOT] = run;
}

__global__ void fill_kernel(const int* __restrict__ ei) {
    int e = blockIdx.x * blockDim.x + threadIdx.x;
    if (e < Ee) {
        int d = ei[Ee + e];
        int p = atomicAdd(&g_cur[d], 1);
        g_csr[p] = ei[e];
    } else if (e < EFULL) {
        int v = e - Ee;
        int p = atomicAdd(&g_cur[v], 1);
        g_csr[p] = v;
    }
}

// ---------------- per-head attention logits ----------------
__global__ void att_kernel(const float* __restrict__ att_src, const float* __restrict__ att_dst,
                           float* __restrict__ asrc, float* __restrict__ adst) {
    int gw   = (blockIdx.x * blockDim.x + threadIdx.x) >> 5;
    int lane = threadIdx.x & 31;
    if (gw >= MTOT) return;
    const float* hr = g_h + (size_t)gw * 128;
    float ps[4], pd[4];
#pragma unroll
    for (int j = 0; j < 4; j++) {
        float hv = hr[j * 32 + lane];
        ps[j] = hv * att_src[j * 32 + lane];
        pd[j] = hv * att_dst[j * 32 + lane];
    }
#pragma unroll
    for (int off = 16; off; off >>= 1)
#pragma unroll
        for (int j = 0; j < 4; j++) {
            ps[j] += __shfl_xor_sync(0xffffffffu, ps[j], off);
            pd[j] += __shfl_xor_sync(0xffffffffu, pd[j], off);
        }
    if (lane == 0)
#pragma unroll
        for (int j = 0; j < 4; j++) {
            asrc[gw * 4 + j] = ps[j];
            adst[gw * 4 + j] = pd[j];
        }
}
__device__ float g_asrc[MTOT * NHEAD];
__device__ float g_adst[MTOT * NHEAD];

// ---------------- GAT edge softmax + aggregation (warp per (node,t)) ----------------
__global__ void gat_kernel(const float* __restrict__ gat_bias) {
    int warp = threadIdx.x >> 5;
    int lane = threadIdx.x & 31;
    int node = blockIdx.x * 8 + warp;
    int t    = blockIdx.y;
    int beg  = g_off[node], end = g_off[node + 1];

    float ad[4];
#pragma unroll
    for (int j = 0; j < 4; j++) ad[j] = g_adst[(t * NTOT + node) * 4 + j];

    float mx[4] = {-1e30f, -1e30f, -1e30f, -1e30f};
    for (int e = beg + lane; e < end; e += 32) {
        int s = g_csr[e];
        const float* as = g_asrc + (t * NTOT + s) * 4;
#pragma unroll
        for (int j = 0; j < 4; j++) {
            float v = as[j] + ad[j];
            v = v > 0.f ? v : 0.2f * v;
            mx[j] = fmaxf(mx[j], v);
        }
    }
#pragma unroll
    for (int off = 16; off; off >>= 1)
#pragma unroll
        for (int j = 0; j < 4; j++) mx[j] = fmaxf(mx[j], __shfl_xor_sync(0xffffffffu, mx[j], off));

    float den[4] = {0.f, 0.f, 0.f, 0.f};
    for (int e = beg + lane; e < end; e += 32) {
        int s = g_csr[e];
        const float* as = g_asrc + (t * NTOT + s) * 4;
#pragma unroll
        for (int j = 0; j < 4; j++) {
            float v = as[j] + ad[j];
            v = v > 0.f ? v : 0.2f * v;
            den[j] += __expf(v - mx[j]);
        }
    }
#pragma unroll
    for (int off = 16; off; off >>= 1)
#pragma unroll
        for (int j = 0; j < 4; j++) den[j] += __shfl_xor_sync(0xffffffffu, den[j], off);

    float rden[4];
#pragma unroll
    for (int j = 0; j < 4; j++) rden[j] = 1.f / den[j];

    float acc[4] = {0.f, 0.f, 0.f, 0.f};
    for (int e = beg; e < end; e++) {
        int s = g_csr[e];
        const float* as = g_asrc + (t * NTOT + s) * 4;
        const float* hs = g_h + (size_t)(t * NTOT + s) * 128;
#pragma unroll
        for (int j = 0; j < 4; j++) {
            float v = as[j] + ad[j];
            v = v > 0.f ? v : 0.2f * v;
            float w = __expf(v - mx[j]) * rden[j];
            acc[j] += w * hs[j * 32 + lane];
        }
    }
#pragma unroll
    for (int j = 0; j < 4; j++) {
        int d = j * 32 + lane;
        float r = fmaxf(acc[j] + gat_bias[d], 0.f);
        split_wr(g_sphi, g_splo, (int)((size_t)(t * NTOT + node) * 128 + d), r);
    }
}

// ---------------- LSTM gate elementwise ----------------
__device__ __forceinline__ float sigmoidf(float x) { return 1.f / (1.f + expf(-x)); }

__global__ void lstm_elem(const float* __restrict__ gates, float* __restrict__ c,
                          float* __restrict__ hf, __half* __restrict__ hhi, __half* __restrict__ hlo) {
    int idx = blockIdx.x * blockDim.x + threadIdx.x;
    if (idx >= NTOT * Hh) return;
    int m = idx >> 7, d = idx & 127;
    const float* g = gates + (size_t)m * 512;
    float si = sigmoidf(g[d]);
    float sf = sigmoidf(g[128 + d]);
    float tg = tanhf(g[256 + d]);
    float so = sigmoidf(g[384 + d]);
    float cn = sf * c[idx] + si * tg;
    c[idx] = cn;
    float hv = so * tanhf(cn);
    hf[idx] = hv;
    split_wr(hhi, hlo, idx, hv);
}

// ---------------- LayerNorm ----------------
__global__ void ln_kernel(const float* __restrict__ gamma, const float* __restrict__ beta,
                          float* __restrict__ out) {
    int gw   = (blockIdx.x * blockDim.x + threadIdx.x) >> 5;
    int lane = threadIdx.x & 31;
    if (gw >= NTOT) return;
    const float* hr = g_h1f + (size_t)gw * 128;
    float v[4];
    float s = 0.f, ss = 0.f;
#pragma unroll
    for (int j = 0; j < 4; j++) {
        v[j] = hr[j * 32 + lane];
        s += v[j];
        ss += v[j] * v[j];
    }
#pragma unroll
    for (int off = 16; off; off >>= 1) {
        s  += __shfl_xor_sync(0xffffffffu, s, off);
        ss += __shfl_xor_sync(0xffffffffu, ss, off);
    }
    float mu   = s * (1.f / 128.f);
    float var  = ss * (1.f / 128.f) - mu * mu;
    float rstd = rsqrtf(var + 1e-5f);
#pragma unroll
    for (int j = 0; j < 4; j++) {
        int d = j * 32 + lane;
        out[(size_t)gw * 128 + d] = (v[j] - mu) * rstd * gamma[d] + beta[d];
    }
}

// ---------------- launch ----------------
template <typename T>
static T* sym(const void* s) { void* p = nullptr; cudaGetSymbolAddress(&p, s); return (T*)p; }

extern "C" void kernel_launch(void* const* d_in, const int* in_sizes, int n_in,
                              void* d_out, int out_size) {
    const float* x        = (const float*)d_in[0];
    const float* W        = (const float*)d_in[1];
    const float* att_src  = (const float*)d_in[2];
    const float* att_dst  = (const float*)d_in[3];
    const float* gat_bias = (const float*)d_in[4];
    const float* W_ih0    = (const float*)d_in[5];
    const float* W_hh0    = (const float*)d_in[6];
    const float* b_ih0    = (const float*)d_in[7];
    const float* b_hh0    = (const float*)d_in[8];
    const float* W_ih1    = (const float*)d_in[9];
    const float* W_hh1    = (const float*)d_in[10];
    const float* b_ih1    = (const float*)d_in[11];
    const float* b_hh1    = (const float*)d_in[12];
    const float* ln_gamma = (const float*)d_in[13];
    const float* ln_beta  = (const float*)d_in[14];
    const int*   edge_index = (const int*)d_in[15];
    float* out = (float*)d_out;

    __half* p_xhi  = sym<__half>(g_xhi);  __half* p_xlo  = sym<__half>(g_xlo);
    __half* p_wthi = sym<__half>(g_wthi); __half* p_wtlo = sym<__half>(g_wtlo);
    __half* p_sphi = sym<__half>(g_sphi); __half* p_splo = sym<__half>(g_splo);
    __half* p_w0hi = sym<__half>(g_w0hi); __half* p_w0lo = sym<__half>(g_w0lo);
    __half* p_u0hi = sym<__half>(g_u0hi); __half* p_u0lo = sym<__half>(g_u0lo);
    __half* p_w1hi = sym<__half>(g_w1hi); __half* p_w1lo = sym<__half>(g_w1lo);
    __half* p_u1hi = sym<__half>(g_u1hi); __half* p_u1lo = sym<__half>(g_u1lo);
    __half* p_h0hi = sym<__half>(g_h0hi); __half* p_h0lo = sym<__half>(g_h0lo);
    __half* p_h1hi = sym<__half>(g_h1hi); __half* p_h1lo = sym<__half>(g_h1lo);
    float* p_h     = sym<float>(g_h);
    float* p_gates = sym<float>(g_gates);
    float* p_c0    = sym<float>(g_c0);
    float* p_c1    = sym<float>(g_c1);
    float* p_h1f   = sym<float>(g_h1f);
    float* p_bsum0 = sym<float>(g_bsum0);
    float* p_bsum1 = sym<float>(g_bsum1);
    float* p_asrc  = sym<float>(g_asrc);
    float* p_adst  = sym<float>(g_adst);

    const int smemB = 2 * BUFB;   // 81920
    cudaFuncSetAttribute(gemm_wm, cudaFuncAttributeMaxDynamicSharedMemorySize, smemB);

    // launches 1-5 (ncu captures launch #6 = the big GEMM)
    transpose_x<<<(MTOT * Ff + 255) / 256, 256>>>(x);
    wt_kernel<<<(Hh * Ff + 255) / 256, 256>>>(W);
    split_w<<<(4 * G4H * Hh + 255) / 256, 256>>>(W_ih0, W_hh0, W_ih1, W_hh1);
    init_kernel<<<(NTOT + 255) / 256, 256>>>(b_ih0, b_hh0, b_ih1, b_hh1);
    zero_state<<<(NTOT * Hh + 255) / 256, 256>>>();

    // launch 6: h = x_flat @ Wt^T  (M=81920, N=128, K=64)
    gemm_wm<<<dim3(1, MTOT / 128), 256, smemB>>>(
        p_xhi, p_xlo, p_wthi, p_wtlo, Ff,
        nullptr, nullptr, nullptr, nullptr, 0, nullptr, p_h, Hh);

    count_kernel<<<(Ee + 255) / 256, 256>>>(edge_index);
    scan_kernel<<<1, 256>>>();
    fill_kernel<<<(EFULL + 255) / 256, 256>>>(edge_index);
    att_kernel<<<(MTOT * 32 + 255) / 256, 256>>>(att_src, att_dst, p_asrc, p_adst);
    gat_kernel<<<dim3(NTOT / 8, Tt), 256>>>(gat_bias);

    for (int t = 0; t < Tt; t++) {
        // layer 0: gates = spatial[t] @ W_ih0^T + h0 @ W_hh0^T + (b_ih0+b_hh0)
        gemm_wm<<<dim3(4, NTOT / 128), 256, smemB>>>(
            p_sphi + (size_t)t * NTOT * Hh, p_splo + (size_t)t * NTOT * Hh,
            p_w0hi, p_w0lo, Hh,
            p_h0hi, p_h0lo, p_u0hi, p_u0lo, Hh,
            p_bsum0, p_gates, G4H);
        lstm_elem<<<(NTOT * Hh + 255) / 256, 256>>>(p_gates, p_c0, p_h1f /*scratch, overwritten by l1*/, p_h0hi, p_h0lo);
        // layer 1: gates = h0 @ W_ih1^T + h1 @ W_hh1^T + (b_ih1+b_hh1)
        gemm_wm<<<dim3(4, NTOT / 128), 256, smemB>>>(
            p_h0hi, p_h0lo, p_w1hi, p_w1lo, Hh,
            p_h1hi, p_h1lo, p_u1hi, p_u1lo, Hh,
            p_bsum1, p_gates, G4H);
        lstm_elem<<<(NTOT * Hh + 255) / 256, 256>>>(p_gates, p_c1, p_h1f, p_h1hi, p_h1lo);
    }

    ln_kernel<<<(NTOT * 32 + 255) / 256, 256>>>(ln_gamma, ln_beta, out);
}